// round 3
// baseline (speedup 1.0000x reference)
#include <cuda_runtime.h>
#include <cuda_bf16.h>
#include <stdint.h>

// Problem constants (fixed by setup_inputs)
// x: (B=8, C=3, H=1024, W=1024) fp32, patch=24, stride=16, reflect pad m=4
// out: patches (B*64*64, 24*24, 3) fp32, plus possibly (nH, nW)=(64,64) flattened.
#define B_   8
#define C_   3
#define H_   1024
#define W_   1024
#define PS_  24
#define ST_  16
#define M_   4
#define NH_  64
#define NW_  64

// 56,623,104 output patch elements — fits in 32-bit unsigned
#define PATCH_ELEMS 56623104u
// per-patch element count = 24*24*3
#define PER_PATCH 1728u

__device__ __forceinline__ int reflect1024(int v) {
    // source coord v in [-4, 1027]; jnp reflect (no edge repeat):
    // v<0 -> -v ; v>=H -> 2*(H-1)-v
    v = (v < 0) ? -v : v;
    v = (v >= H_) ? (2 * (H_ - 1) - v) : v;
    return v;
}

__device__ __forceinline__ float gather_one(const float* __restrict__ x, unsigned e) {
    if (e >= PATCH_ELEMS) return 64.0f;        // trailing (nH, nW) slots, if present
    unsigned patch = e / PER_PATCH;            // magic-mul
    unsigned r     = e - patch * PER_PATCH;    // 0..1727
    unsigned c     = r % 3u;
    unsigned pj    = r / 3u;                   // 0..575
    unsigned i     = pj / 24u;                 // row within patch
    unsigned j     = pj - i * 24u;             // col within patch
    unsigned pw    = patch & 63u;
    unsigned ph    = (patch >> 6) & 63u;
    unsigned b     = patch >> 12;

    int y = reflect1024((int)(ph * ST_ + i) - M_);
    int xc = reflect1024((int)(pw * ST_ + j) - M_);

    unsigned idx = (((b * 3u + c) << 10) + (unsigned)y) * 1024u + (unsigned)xc;
    return __ldg(x + idx);
}

__global__ __launch_bounds__(256)
void Patcher_78280073937146_kernel(const float* __restrict__ x,
                                   float* __restrict__ out,
                                   unsigned out_elems) {
    unsigned t = blockIdx.x * 256u + threadIdx.x;
    unsigned e0 = t << 2;                      // 4 elements per thread
    if (e0 >= out_elems) return;

    if (e0 + 3u < out_elems) {
        float4 v;
        v.x = gather_one(x, e0 + 0u);
        v.y = gather_one(x, e0 + 1u);
        v.z = gather_one(x, e0 + 2u);
        v.w = gather_one(x, e0 + 3u);
        // out base is 16B-aligned and e0 is a multiple of 4 -> STG.128 valid
        reinterpret_cast<float4*>(out)[t] = v;
    } else {
        // scalar tail (handles out_elems % 4 != 0, e.g. +2 for (nH, nW))
        #pragma unroll
        for (unsigned k = 0; k < 4u; ++k) {
            unsigned e = e0 + k;
            if (e < out_elems) out[e] = gather_one(x, e);
        }
    }
}

extern "C" void kernel_launch(void* const* d_in, const int* in_sizes, int n_in,
                              void* d_out, int out_size) {
    const float* x = (const float*)d_in[0];
    float* out = (float*)d_out;
    unsigned out_elems = (unsigned)out_size;
    unsigned n4 = (out_elems + 3u) >> 2;       // threads (4 elems each)
    unsigned blocks = (n4 + 255u) / 256u;
    Patcher_78280073937146_kernel<<<blocks, 256>>>(x, out, out_elems);
}

// round 4
// speedup vs baseline: 1.1112x; 1.1112x over previous
#include <cuda_runtime.h>
#include <cuda_bf16.h>
#include <stdint.h>

// x: (B=8, C=3, H=1024, W=1024) fp32; patch=24, stride=16, reflect pad m=4
// out: (8*64*64, 576, 3) fp32 row-major = 56,623,104 elems, then (nH,nW)=(64,64).
#define PATCH_ELEMS 56623104u
#define TOTAL_QUADS 4718592u   // PATCH_ELEMS / 12  (one thread = 4 pixels x 3 ch)

__device__ __forceinline__ int reflect1024(int v) {
    v = (v < 0) ? -v : v;                 // jnp 'reflect' (no edge repeat)
    v = (v >= 1024) ? (2046 - v) : v;
    return v;
}

__global__ __launch_bounds__(256)
void Patcher_78280073937146_kernel(const float* __restrict__ x,
                                   float* __restrict__ out,
                                   unsigned out_elems) {
    unsigned g = blockIdx.x * 256u + threadIdx.x;

    if (g < TOTAL_QUADS) {
        // ---- decode: patch + pixel-quad ----
        unsigned patch = g / 144u;            // 144 quads per patch (576 px / 4)
        unsigned u     = g - patch * 144u;    // 0..143
        unsigned iu    = u / 6u;              // patch row 0..23
        unsigned jq    = u - iu * 6u;         // col-quad 0..5
        unsigned j0    = jq << 2;             // 0,4,...,20

        unsigned b  = patch >> 12;
        unsigned ph = (patch >> 6) & 63u;
        unsigned pw = patch & 63u;

        int y  = reflect1024((int)(ph * 16u + iu) - 4);
        int x0 = (int)(pw * 16u + j0) - 4;    // -4, 0..1020 (step 4), or 1024

        unsigned planeBase = (b * 3u) << 20;  // (b*3+c)*1024*1024
        unsigned rowOff    = ((unsigned)y) << 10;

        float4 r0, r1, r2;                    // channel planes, pixels p0..p3
        if ((unsigned)x0 <= 1020u) {
            // common case: 4 contiguous, 16B-aligned source pixels per plane
            unsigned a = planeBase + rowOff + (unsigned)x0;
            r0 = *reinterpret_cast<const float4*>(x + a);
            r1 = *reinterpret_cast<const float4*>(x + a + (1u << 20));
            r2 = *reinterpret_cast<const float4*>(x + a + (2u << 20));
        } else {
            // reflected edge (x0 == -4 or 1024): contiguous-reversed, scalar
            float v0[4], v1[4], v2[4];
            #pragma unroll
            for (int k = 0; k < 4; ++k) {
                unsigned a = planeBase + rowOff + (unsigned)reflect1024(x0 + k);
                v0[k] = x[a];
                v1[k] = x[a + (1u << 20)];
                v2[k] = x[a + (2u << 20)];
            }
            r0 = make_float4(v0[0], v0[1], v0[2], v0[3]);
            r1 = make_float4(v1[0], v1[1], v1[2], v1[3]);
            r2 = make_float4(v2[0], v2[1], v2[2], v2[3]);
        }

        // ---- permute channel-major -> (pixel, channel) interleaved ----
        float4 o0 = make_float4(r0.x, r1.x, r2.x, r0.y);
        float4 o1 = make_float4(r1.y, r2.y, r0.z, r1.z);
        float4 o2 = make_float4(r2.z, r0.w, r1.w, r2.w);

        float4* ov = reinterpret_cast<float4*>(out) + (size_t)g * 3u;
        ov[0] = o0;
        ov[1] = o1;
        ov[2] = o2;
    } else {
        // trailing (nH, nW) = (64, 64) slots, if the harness appends them
        unsigned e = PATCH_ELEMS + (g - TOTAL_QUADS);
        if (e < out_elems) out[e] = 64.0f;
    }
}

extern "C" void kernel_launch(void* const* d_in, const int* in_sizes, int n_in,
                              void* d_out, int out_size) {
    const float* x = (const float*)d_in[0];
    float* out = (float*)d_out;
    unsigned out_elems = (unsigned)out_size;

    unsigned mainBlocks = TOTAL_QUADS / 256u;                 // 18432 exact
    unsigned extraElems = (out_elems > PATCH_ELEMS) ? (out_elems - PATCH_ELEMS) : 0u;
    unsigned extraBlocks = (extraElems + 255u) / 256u;
    Patcher_78280073937146_kernel<<<mainBlocks + extraBlocks, 256>>>(x, out, out_elems);
}